// round 4
// baseline (speedup 1.0000x reference)
#include <cuda_runtime.h>

#define BATCH 2
#define SEQ   2048
#define DM    1024
#define NH    16
#define DH    64
#define MTOT  (BATCH * SEQ)   // 4096

#define BM 128
#define BN 128
#define BK 8

#define AT_LD 68   // float rows: 64 + 4 pad (16B-aligned rows)
#define AT_LD2 66  // u64 rows: 64 + 2 pad (16B-aligned rows)

typedef unsigned long long u64;

// ---------------------------------------------------------------------------
// packed fp32x2 helpers (Blackwell FFMA2 path)
// ---------------------------------------------------------------------------
__device__ __forceinline__ u64 pk2(float v) {
    u64 r; asm("mov.b64 %0, {%1, %1};" : "=l"(r) : "f"(v)); return r;
}
__device__ __forceinline__ float2 upk2(u64 v) {
    float2 f; asm("mov.b64 {%0, %1}, %2;" : "=f"(f.x), "=f"(f.y) : "l"(v)); return f;
}
__device__ __forceinline__ void fma2(u64& c, u64 a, u64 b) {
    asm("fma.rn.f32x2 %0, %1, %2, %0;" : "+l"(c) : "l"(a), "l"(b));
}
__device__ __forceinline__ void mul2(u64& c, u64 a) {
    asm("mul.rn.f32x2 %0, %0, %1;" : "+l"(c) : "l"(a));
}

// scratch (allocation-free rule: __device__ globals)
__device__ float g_Q[BATCH * NH * SEQ * DH];
__device__ float g_K[BATCH * NH * SEQ * DH];
__device__ float g_V[BATCH * NH * SEQ * DH];
__device__ float g_H[MTOT * DM];

// ---------------------------------------------------------------------------
// SGEMM core: 128x128 tile, 8x8 per thread (as 8x4 f32x2 pairs), BK=8,
// double-buffered smem. A staged REPLICATED as (v,v) u64 pairs so the inner
// loop is LDS.128 + FFMA2 only.
// ---------------------------------------------------------------------------
__device__ __forceinline__ void sgemm_tile(const float* __restrict__ A,
                                           const float* __restrict__ B,
                                           int m0, int n0, int lda, int ldb,
                                           u64 acc[8][4]) {
    __shared__ __align__(16) u64   As2[2][BK][BM];
    __shared__ __align__(16) float Bs[2][BK][BN];

    const int tid  = threadIdx.x;
    const int arow = tid >> 1;          // 0..127
    const int ak   = (tid & 1) << 2;    // 0 or 4
    const int bkr  = tid >> 5;          // 0..7
    const int bcol = (tid & 31) << 2;   // 0..124
    const int ty   = tid >> 4;          // 0..15
    const int tx   = tid & 15;          // 0..15

    const float* Ap = A + (size_t)(m0 + arow) * lda + ak;
    const float* Bp = B + (size_t)bkr * ldb + n0 + bcol;

    // prologue: tile 0
    {
        float4 av = *(const float4*)Ap;
        float4 bv = *(const float4*)Bp;
        As2[0][ak + 0][arow] = pk2(av.x);
        As2[0][ak + 1][arow] = pk2(av.y);
        As2[0][ak + 2][arow] = pk2(av.z);
        As2[0][ak + 3][arow] = pk2(av.w);
        *(float4*)&Bs[0][bkr][bcol] = bv;
    }
    __syncthreads();

    int buf = 0;
    for (int kt = BK; kt <= DM; kt += BK) {
        float4 av2, bv2;
        const bool more = (kt < DM);
        if (more) {
            av2 = *(const float4*)(Ap + kt);
            bv2 = *(const float4*)(Bp + (size_t)kt * ldb);
        }
        #pragma unroll
        for (int k = 0; k < BK; k++) {
            ulonglong2 a01 = *(const ulonglong2*)&As2[buf][k][(ty << 2) + 0];
            ulonglong2 a23 = *(const ulonglong2*)&As2[buf][k][(ty << 2) + 2];
            ulonglong2 a45 = *(const ulonglong2*)&As2[buf][k][64 + (ty << 2) + 0];
            ulonglong2 a67 = *(const ulonglong2*)&As2[buf][k][64 + (ty << 2) + 2];
            ulonglong2 b01 = *(const ulonglong2*)&Bs[buf][k][tx << 2];
            ulonglong2 b23 = *(const ulonglong2*)&Bs[buf][k][64 + (tx << 2)];
            u64 aa[8] = {a01.x, a01.y, a23.x, a23.y, a45.x, a45.y, a67.x, a67.y};
            u64 bb[4] = {b01.x, b01.y, b23.x, b23.y};
            #pragma unroll
            for (int i = 0; i < 8; i++) {
                fma2(acc[i][0], aa[i], bb[0]);
                fma2(acc[i][1], aa[i], bb[1]);
                fma2(acc[i][2], aa[i], bb[2]);
                fma2(acc[i][3], aa[i], bb[3]);
            }
        }
        if (more) {
            buf ^= 1;
            As2[buf][ak + 0][arow] = pk2(av2.x);
            As2[buf][ak + 1][arow] = pk2(av2.y);
            As2[buf][ak + 2][arow] = pk2(av2.z);
            As2[buf][ak + 3][arow] = pk2(av2.w);
            *(float4*)&Bs[buf][bkr][bcol] = bv2;
            __syncthreads();
        }
    }
}

// ---------------------------------------------------------------------------
// QKV projections: y = x @ W + b, scattered to [B, H, S, Dh]
// ---------------------------------------------------------------------------
__global__ __launch_bounds__(256, 2)
void qkv_gemm_kernel(const float* __restrict__ x,
                     const float* __restrict__ Wq, const float* __restrict__ bq,
                     const float* __restrict__ Wk, const float* __restrict__ bk,
                     const float* __restrict__ Wv, const float* __restrict__ bv) {
    const int m0 = blockIdx.y << 7;
    const int n0 = blockIdx.x << 7;
    const int which = blockIdx.z;
    const float* W    = (which == 0) ? Wq : (which == 1) ? Wk : Wv;
    const float* bias = (which == 0) ? bq : (which == 1) ? bk : bv;
    float* out        = (which == 0) ? g_Q : (which == 1) ? g_K : g_V;

    u64 acc[8][4] = {};
    sgemm_tile(x, W, m0, n0, DM, DM, acc);

    const int ty = threadIdx.x >> 4;
    const int tx = threadIdx.x & 15;
    #pragma unroll
    for (int ih = 0; ih < 2; ih++) {
        #pragma unroll
        for (int i = 0; i < 4; i++) {
            const int m = m0 + ih * 64 + (ty << 2) + i;
            const int b = m >> 11;
            const int s = m & (SEQ - 1);
            #pragma unroll
            for (int jh = 0; jh < 2; jh++) {
                const int n = n0 + jh * 64 + (tx << 2);
                const int h = n >> 6;
                const int d = n & 63;
                float2 p0 = upk2(acc[ih * 4 + i][jh * 2 + 0]);
                float2 p1 = upk2(acc[ih * 4 + i][jh * 2 + 1]);
                float4 o = make_float4(p0.x + bias[n + 0], p0.y + bias[n + 1],
                                       p1.x + bias[n + 2], p1.y + bias[n + 3]);
                *(float4*)&out[((size_t)((b * NH + h) * SEQ + s) << 6) + d] = o;
            }
        }
    }
}

// ---------------------------------------------------------------------------
// Output projection: out = g_H @ Wo + bo
// ---------------------------------------------------------------------------
__global__ __launch_bounds__(256, 2)
void out_gemm_kernel(const float* __restrict__ Wo, const float* __restrict__ bo,
                     float* __restrict__ out) {
    const int m0 = blockIdx.y << 7;
    const int n0 = blockIdx.x << 7;

    u64 acc[8][4] = {};
    sgemm_tile(g_H, Wo, m0, n0, DM, DM, acc);

    const int ty = threadIdx.x >> 4;
    const int tx = threadIdx.x & 15;
    #pragma unroll
    for (int ih = 0; ih < 2; ih++) {
        #pragma unroll
        for (int i = 0; i < 4; i++) {
            const int m = m0 + ih * 64 + (ty << 2) + i;
            #pragma unroll
            for (int jh = 0; jh < 2; jh++) {
                const int n = n0 + jh * 64 + (tx << 2);
                float2 p0 = upk2(acc[ih * 4 + i][jh * 2 + 0]);
                float2 p1 = upk2(acc[ih * 4 + i][jh * 2 + 1]);
                float4 o = make_float4(p0.x + bo[n + 0], p0.y + bo[n + 1],
                                       p1.x + bo[n + 2], p1.y + bo[n + 3]);
                *(float4*)&out[(size_t)m * DM + n] = o;
            }
        }
    }
}

// ---------------------------------------------------------------------------
// Causal flash attention with f32x2 packed math.
// Q staged transposed+replicated (u64), K transposed (f32), V natural (f32),
// P staged replicated (u64). Thread (ty,tx) owns 4x4 score / O tile.
// ---------------------------------------------------------------------------
__global__ __launch_bounds__(256)
void attn_kernel() {
    extern __shared__ __align__(16) char smraw[];
    u64*   Qt2 = (u64*)smraw;                        // [64][AT_LD2] Qt2[d][r]=(q,q)
    float* Kt  = (float*)(Qt2 + 64 * AT_LD2);        // [64][AT_LD]  Kt[d][c]
    float* Vs  = Kt + 64 * AT_LD;                    // [64][AT_LD]  Vs[k][d]
    u64*   Ps2 = (u64*)(Vs + 64 * AT_LD);            // [64][AT_LD2] Ps2[r][k]=(p,p)

    const int qt = (gridDim.x - 1) - blockIdx.x;     // heavy tiles first
    const int bh = blockIdx.y;
    const int b  = bh / NH;
    const int h  = bh % NH;

    const float* Qg = g_Q + (size_t)(bh * SEQ + (qt << 6)) * DH;
    const float* Kg = g_K + (size_t)bh * SEQ * DH;
    const float* Vg = g_V + (size_t)bh * SEQ * DH;

    const int tid = threadIdx.x;
    const int ty  = tid >> 4;
    const int tx  = tid & 15;
    const int lr  = tid >> 2;          // loader row 0..63
    const int ld0 = (tid & 3) << 4;    // loader dim start

    // load Q tile transposed + replicated: Qt2[d][r] = (Q[r][d], Q[r][d])
    {
        const float* qp = Qg + lr * DH + ld0;
        #pragma unroll
        for (int q = 0; q < 16; q += 4) {
            float4 v = *(const float4*)(qp + q);
            Qt2[(ld0 + q + 0) * AT_LD2 + lr] = pk2(v.x);
            Qt2[(ld0 + q + 1) * AT_LD2 + lr] = pk2(v.y);
            Qt2[(ld0 + q + 2) * AT_LD2 + lr] = pk2(v.z);
            Qt2[(ld0 + q + 3) * AT_LD2 + lr] = pk2(v.w);
        }
    }

    u64 O2[4][2] = {};                 // O pairs along dh
    float mrun[4], lrun[4];
    #pragma unroll
    for (int i = 0; i < 4; i++) { mrun[i] = -1e30f; lrun[i] = 0.f; }
    const float scale = 0.125f;        // 1/sqrt(64)
    const int qrow0 = (qt << 6) + (ty << 2);

    for (int kt = 0; kt <= qt; kt++) {
        __syncthreads();
        // load K transposed + V natural
        {
            const float* kp = Kg + (size_t)((kt << 6) + lr) * DH + ld0;
            const float* vp = Vg + (size_t)((kt << 6) + lr) * DH + ld0;
            #pragma unroll
            for (int q = 0; q < 16; q += 4) {
                float4 kv = *(const float4*)(kp + q);
                Kt[(ld0 + q + 0) * AT_LD + lr] = kv.x;
                Kt[(ld0 + q + 1) * AT_LD + lr] = kv.y;
                Kt[(ld0 + q + 2) * AT_LD + lr] = kv.z;
                Kt[(ld0 + q + 3) * AT_LD + lr] = kv.w;
                *(float4*)&Vs[lr * AT_LD + ld0 + q] = *(const float4*)(vp + q);
            }
        }
        __syncthreads();

        // scores: s2[i][·] pairs over k-columns
        u64 s2[4][2] = {};
        #pragma unroll 16
        for (int d = 0; d < 64; d++) {
            ulonglong2 qa = *(const ulonglong2*)&Qt2[d * AT_LD2 + (ty << 2) + 0];
            ulonglong2 qb = *(const ulonglong2*)&Qt2[d * AT_LD2 + (ty << 2) + 2];
            ulonglong2 kv = *(const ulonglong2*)&Kt[d * AT_LD + (tx << 2)];
            fma2(s2[0][0], qa.x, kv.x); fma2(s2[0][1], qa.x, kv.y);
            fma2(s2[1][0], qa.y, kv.x); fma2(s2[1][1], qa.y, kv.y);
            fma2(s2[2][0], qb.x, kv.x); fma2(s2[2][1], qb.x, kv.y);
            fma2(s2[3][0], qb.y, kv.x); fma2(s2[3][1], qb.y, kv.y);
        }

        // unpack scores
        float s[4][4];
        #pragma unroll
        for (int i = 0; i < 4; i++) {
            float2 a = upk2(s2[i][0]);
            float2 c = upk2(s2[i][1]);
            s[i][0] = a.x; s[i][1] = a.y; s[i][2] = c.x; s[i][3] = c.y;
        }

        // scale (+ causal mask on the diagonal tile only)
        if (kt == qt) {
            #pragma unroll
            for (int i = 0; i < 4; i++) {
                const int qg = qrow0 + i;
                #pragma unroll
                for (int j = 0; j < 4; j++) {
                    const int kg = (kt << 6) + (tx << 2) + j;
                    s[i][j] = (kg <= qg) ? s[i][j] * scale : -1e30f;
                }
            }
        } else {
            #pragma unroll
            for (int i = 0; i < 4; i++)
                #pragma unroll
                for (int j = 0; j < 4; j++) s[i][j] *= scale;
        }

        // online softmax per row (reduce across 16 tx lanes)
        #pragma unroll
        for (int i = 0; i < 4; i++) {
            float m = fmaxf(fmaxf(s[i][0], s[i][1]), fmaxf(s[i][2], s[i][3]));
            m = fmaxf(m, __shfl_xor_sync(0xffffffffu, m, 1));
            m = fmaxf(m, __shfl_xor_sync(0xffffffffu, m, 2));
            m = fmaxf(m, __shfl_xor_sync(0xffffffffu, m, 4));
            m = fmaxf(m, __shfl_xor_sync(0xffffffffu, m, 8));
            const float mnew  = fmaxf(mrun[i], m);
            const float alpha = __expf(mrun[i] - mnew);
            float l = 0.f;
            #pragma unroll
            for (int j = 0; j < 4; j++) {
                s[i][j] = __expf(s[i][j] - mnew);
                l += s[i][j];
            }
            l += __shfl_xor_sync(0xffffffffu, l, 1);
            l += __shfl_xor_sync(0xffffffffu, l, 2);
            l += __shfl_xor_sync(0xffffffffu, l, 4);
            l += __shfl_xor_sync(0xffffffffu, l, 8);
            lrun[i] = lrun[i] * alpha + l;
            mrun[i] = mnew;
            u64 al2 = pk2(alpha);
            mul2(O2[i][0], al2);
            mul2(O2[i][1], al2);
            // stage P replicated (warp-local rows)
            Ps2[((ty << 2) + i) * AT_LD2 + (tx << 2) + 0] = pk2(s[i][0]);
            Ps2[((ty << 2) + i) * AT_LD2 + (tx << 2) + 1] = pk2(s[i][1]);
            Ps2[((ty << 2) + i) * AT_LD2 + (tx << 2) + 2] = pk2(s[i][2]);
            Ps2[((ty << 2) + i) * AT_LD2 + (tx << 2) + 3] = pk2(s[i][3]);
        }
        __syncwarp();

        // O[i][·] += sum_k P[4ty+i][k] * V[k][·]
        #pragma unroll 4
        for (int k4 = 0; k4 < 64; k4 += 4) {
            u64 parr[4][4];
            #pragma unroll
            for (int i = 0; i < 4; i++) {
                ulonglong2 pa = *(const ulonglong2*)&Ps2[((ty << 2) + i) * AT_LD2 + k4 + 0];
                ulonglong2 pb = *(const ulonglong2*)&Ps2[((ty << 2) + i) * AT_LD2 + k4 + 2];
                parr[i][0] = pa.x; parr[i][1] = pa.y;
                parr[i][2] = pb.x; parr[i][3] = pb.y;
            }
            #pragma unroll
            for (int t = 0; t < 4; t++) {
                ulonglong2 v2 = *(const ulonglong2*)&Vs[(k4 + t) * AT_LD + (tx << 2)];
                fma2(O2[0][0], parr[0][t], v2.x); fma2(O2[0][1], parr[0][t], v2.y);
                fma2(O2[1][0], parr[1][t], v2.x); fma2(O2[1][1], parr[1][t], v2.y);
                fma2(O2[2][0], parr[2][t], v2.x); fma2(O2[2][1], parr[2][t], v2.y);
                fma2(O2[3][0], parr[3][t], v2.x); fma2(O2[3][1], parr[3][t], v2.y);
            }
        }
    }

    // epilogue: normalize, write to g_H [B, S, D]
    #pragma unroll
    for (int i = 0; i < 4; i++) {
        const float inv = 1.0f / lrun[i];
        float2 a = upk2(O2[i][0]);
        float2 c = upk2(O2[i][1]);
        float* outp = g_H + (size_t)(b * SEQ + (qt << 6) + (ty << 2) + i) * DM
                          + h * DH + (tx << 2);
        *(float4*)outp = make_float4(a.x * inv, a.y * inv, c.x * inv, c.y * inv);
    }
}

// ---------------------------------------------------------------------------
extern "C" void kernel_launch(void* const* d_in, const int* in_sizes, int n_in,
                              void* d_out, int out_size) {
    const float* x  = (const float*)d_in[0];
    const float* Wq = (const float*)d_in[1];
    const float* bq = (const float*)d_in[2];
    const float* Wk = (const float*)d_in[3];
    const float* bk = (const float*)d_in[4];
    const float* Wv = (const float*)d_in[5];
    const float* bv = (const float*)d_in[6];
    const float* Wo = (const float*)d_in[7];
    const float* bo = (const float*)d_in[8];
    float* out = (float*)d_out;

    // 1. QKV projections
    dim3 gq(DM / BN, MTOT / BM, 3);
    qkv_gemm_kernel<<<gq, 256>>>(x, Wq, bq, Wk, bk, Wv, bv);

    // 2. causal flash attention
    const size_t smem = (size_t)(2 * 64 * AT_LD2) * sizeof(u64)
                      + (size_t)(2 * 64 * AT_LD) * sizeof(float);
    cudaFuncSetAttribute(attn_kernel, cudaFuncAttributeMaxDynamicSharedMemorySize,
                         (int)smem);
    attn_kernel<<<dim3(SEQ / 64, BATCH * NH), 256, smem>>>();

    // 3. output projection
    out_gemm_kernel<<<dim3(DM / BN, MTOT / BM), 256>>>(Wo, bo, out);
}

// round 5
// speedup vs baseline: 1.1605x; 1.1605x over previous
#include <cuda_runtime.h>
#include <cstdint>

#define BATCH 2
#define SEQ   2048
#define DM    1024
#define NH    16
#define DH    64
#define MTOT  (BATCH * SEQ)   // 4096

#define BM 128
#define BN 128
#define BK 16

// attention tiles
#define QT 128
#define KTILE 64
#define QT_LD 132   // 128 + 4 pad
#define KV_LD 68    // 64 + 4 pad

// scratch (allocation-free rule: __device__ globals)
__device__ float g_Q[BATCH * NH * SEQ * DH];
__device__ float g_K[BATCH * NH * SEQ * DH];
__device__ float g_V[BATCH * NH * SEQ * DH];
__device__ float g_H[MTOT * DM];

// ---------------------------------------------------------------------------
// cp.async helpers
// ---------------------------------------------------------------------------
__device__ __forceinline__ uint32_t smaddr(const void* p) {
    return (uint32_t)__cvta_generic_to_shared(p);
}
__device__ __forceinline__ void cpa16(uint32_t s, const void* g) {
    asm volatile("cp.async.cg.shared.global [%0], [%1], 16;" :: "r"(s), "l"(g));
}
__device__ __forceinline__ void cpa_commit() {
    asm volatile("cp.async.commit_group;");
}
__device__ __forceinline__ void cpa_wait0() {
    asm volatile("cp.async.wait_group 0;");
}

// ---------------------------------------------------------------------------
// SGEMM core: 128x128 tile, 8x8 per thread, BK=16, double-buffered.
// B loaded via cp.async (no register staging); A via LDG + transposed STS.
// ---------------------------------------------------------------------------
__device__ __forceinline__ void sgemm_tile(const float* __restrict__ A,
                                           const float* __restrict__ B,
                                           int m0, int n0, int lda, int ldb,
                                           float acc[8][8]) {
    __shared__ __align__(16) float As[2][BK][BM];
    __shared__ __align__(16) float Bs[2][BK][BN];

    const int tid  = threadIdx.x;
    const int arow = tid >> 1;          // 0..127
    const int ak   = (tid & 1) << 3;    // 0 or 8
    const int brow = tid >> 4;          // 0..15
    const int bcol = (tid & 15) << 3;   // 0..120 step 8
    const int ty   = tid >> 4;          // 0..15
    const int tx   = tid & 15;          // 0..15

    const float* Ap = A + (size_t)(m0 + arow) * lda + ak;
    const float* Bp = B + (size_t)brow * ldb + n0 + bcol;

    // prologue: tile 0
    {
        float4 a0 = *(const float4*)Ap;
        float4 a1 = *(const float4*)(Ap + 4);
        As[0][ak + 0][arow] = a0.x;  As[0][ak + 1][arow] = a0.y;
        As[0][ak + 2][arow] = a0.z;  As[0][ak + 3][arow] = a0.w;
        As[0][ak + 4][arow] = a1.x;  As[0][ak + 5][arow] = a1.y;
        As[0][ak + 6][arow] = a1.z;  As[0][ak + 7][arow] = a1.w;
        cpa16(smaddr(&Bs[0][brow][bcol]),     Bp);
        cpa16(smaddr(&Bs[0][brow][bcol + 4]), Bp + 4);
        cpa_commit();
        cpa_wait0();
    }
    __syncthreads();

    int buf = 0;
    for (int kt = BK; kt <= DM; kt += BK) {
        const bool more = (kt < DM);
        float4 a0, a1;
        if (more) {
            a0 = *(const float4*)(Ap + kt);
            a1 = *(const float4*)(Ap + kt + 4);
            const float* bp = Bp + (size_t)kt * ldb;
            cpa16(smaddr(&Bs[buf ^ 1][brow][bcol]),     bp);
            cpa16(smaddr(&Bs[buf ^ 1][brow][bcol + 4]), bp + 4);
            cpa_commit();
        }
        #pragma unroll
        for (int k = 0; k < BK; k++) {
            float a[8], b[8];
            *(float4*)&a[0] = *(const float4*)&As[buf][k][ty << 2];
            *(float4*)&a[4] = *(const float4*)&As[buf][k][64 + (ty << 2)];
            *(float4*)&b[0] = *(const float4*)&Bs[buf][k][tx << 2];
            *(float4*)&b[4] = *(const float4*)&Bs[buf][k][64 + (tx << 2)];
            #pragma unroll
            for (int i = 0; i < 8; i++)
                #pragma unroll
                for (int j = 0; j < 8; j++)
                    acc[i][j] = fmaf(a[i], b[j], acc[i][j]);
        }
        if (more) {
            buf ^= 1;
            As[buf][ak + 0][arow] = a0.x;  As[buf][ak + 1][arow] = a0.y;
            As[buf][ak + 2][arow] = a0.z;  As[buf][ak + 3][arow] = a0.w;
            As[buf][ak + 4][arow] = a1.x;  As[buf][ak + 5][arow] = a1.y;
            As[buf][ak + 6][arow] = a1.z;  As[buf][ak + 7][arow] = a1.w;
            cpa_wait0();
            __syncthreads();
        }
    }
}

// ---------------------------------------------------------------------------
// QKV projections: y = x @ W + b, scattered to [B, H, S, Dh]
// ---------------------------------------------------------------------------
__global__ __launch_bounds__(256, 2)
void qkv_gemm_kernel(const float* __restrict__ x,
                     const float* __restrict__ Wq, const float* __restrict__ bq,
                     const float* __restrict__ Wk, const float* __restrict__ bk,
                     const float* __restrict__ Wv, const float* __restrict__ bv) {
    const int m0 = blockIdx.y << 7;
    const int n0 = blockIdx.x << 7;
    const int which = blockIdx.z;
    const float* W    = (which == 0) ? Wq : (which == 1) ? Wk : Wv;
    const float* bias = (which == 0) ? bq : (which == 1) ? bk : bv;
    float* out        = (which == 0) ? g_Q : (which == 1) ? g_K : g_V;

    float acc[8][8] = {};
    sgemm_tile(x, W, m0, n0, DM, DM, acc);

    const int ty = threadIdx.x >> 4;
    const int tx = threadIdx.x & 15;
    #pragma unroll
    for (int ih = 0; ih < 2; ih++) {
        #pragma unroll
        for (int i = 0; i < 4; i++) {
            const int m = m0 + ih * 64 + (ty << 2) + i;
            const int b = m >> 11;
            const int s = m & (SEQ - 1);
            #pragma unroll
            for (int jh = 0; jh < 2; jh++) {
                const int n = n0 + jh * 64 + (tx << 2);
                const int h = n >> 6;
                const int d = n & 63;
                float4 o = make_float4(acc[ih * 4 + i][jh * 4 + 0] + bias[n + 0],
                                       acc[ih * 4 + i][jh * 4 + 1] + bias[n + 1],
                                       acc[ih * 4 + i][jh * 4 + 2] + bias[n + 2],
                                       acc[ih * 4 + i][jh * 4 + 3] + bias[n + 3]);
                *(float4*)&out[((size_t)((b * NH + h) * SEQ + s) << 6) + d] = o;
            }
        }
    }
}

// ---------------------------------------------------------------------------
// Output projection: out = g_H @ Wo + bo
// ---------------------------------------------------------------------------
__global__ __launch_bounds__(256, 2)
void out_gemm_kernel(const float* __restrict__ Wo, const float* __restrict__ bo,
                     float* __restrict__ out) {
    const int m0 = blockIdx.y << 7;
    const int n0 = blockIdx.x << 7;

    float acc[8][8] = {};
    sgemm_tile(g_H, Wo, m0, n0, DM, DM, acc);

    const int ty = threadIdx.x >> 4;
    const int tx = threadIdx.x & 15;
    #pragma unroll
    for (int ih = 0; ih < 2; ih++) {
        #pragma unroll
        for (int i = 0; i < 4; i++) {
            const int m = m0 + ih * 64 + (ty << 2) + i;
            #pragma unroll
            for (int jh = 0; jh < 2; jh++) {
                const int n = n0 + jh * 64 + (tx << 2);
                float4 o = make_float4(acc[ih * 4 + i][jh * 4 + 0] + bo[n + 0],
                                       acc[ih * 4 + i][jh * 4 + 1] + bo[n + 1],
                                       acc[ih * 4 + i][jh * 4 + 2] + bo[n + 2],
                                       acc[ih * 4 + i][jh * 4 + 3] + bo[n + 3]);
                *(float4*)&out[(size_t)m * DM + n] = o;
            }
        }
    }
}

// ---------------------------------------------------------------------------
// Causal flash attention: q-tile 128 x k-tile 64, 256 threads.
// Thread (ty=tid>>4, tx=tid&15) owns scores s[8 rows][4 cols] for rows
// 8ty..8ty+7 and cols 4tx..4tx+3, and O[8 rows][4 dh] for dh 4tx..4tx+3.
// Q,K staged transposed; V natural; P staged natural (row-aligned float4).
// ---------------------------------------------------------------------------
__global__ __launch_bounds__(256, 2)
void attn_kernel() {
    extern __shared__ float smf[];
    float* Qt = smf;                   // [64][QT_LD]  Qt[d][r]
    float* Kt = Qt + 64 * QT_LD;       // [64][KV_LD]  Kt[d][c]
    float* Vs = Kt + 64 * KV_LD;       // [64][KV_LD]  Vs[k][d]
    float* Ps = Vs + 64 * KV_LD;       // [128][KV_LD] Ps[r][k]

    const int qt = (gridDim.x - 1) - blockIdx.x;  // heavy tiles first
    const int bh = blockIdx.y;
    const int b  = bh / NH;
    const int h  = bh % NH;
    const int qb = qt * QT;

    const float* Qg = g_Q + (size_t)(bh * SEQ + qb) * DH;
    const float* Kg = g_K + (size_t)bh * SEQ * DH;
    const float* Vg = g_V + (size_t)bh * SEQ * DH;

    const int tid = threadIdx.x;
    const int ty  = tid >> 4;          // 0..15 -> rows 8ty..8ty+7
    const int tx  = tid & 15;          // 0..15 -> cols 4tx..4tx+3

    // load Q tile [128 x 64] transposed: Qt[d][r]
    {
        const int r  = tid >> 1;             // 0..127
        const int c0 = (tid & 1) << 5;       // 0 or 32
        const float* qp = Qg + (size_t)r * DH + c0;
        #pragma unroll
        for (int q = 0; q < 32; q += 4) {
            float4 v = *(const float4*)(qp + q);
            Qt[(c0 + q + 0) * QT_LD + r] = v.x;
            Qt[(c0 + q + 1) * QT_LD + r] = v.y;
            Qt[(c0 + q + 2) * QT_LD + r] = v.z;
            Qt[(c0 + q + 3) * QT_LD + r] = v.w;
        }
    }

    float O[8][4];
    float mrun[8], lrun[8];
    #pragma unroll
    for (int i = 0; i < 8; i++) {
        mrun[i] = -1e30f; lrun[i] = 0.f;
        #pragma unroll
        for (int j = 0; j < 4; j++) O[i][j] = 0.f;
    }
    const float scale = 0.125f;        // 1/sqrt(64)
    const int ktmax = 2 * qt + 1;

    for (int kt = 0; kt <= ktmax; kt++) {
        __syncthreads();
        // load K transposed + V natural (tile [64 x 64])
        {
            const int lr = tid >> 2;           // 0..63
            const int c0 = (tid & 3) << 4;     // 0,16,32,48
            const float* kp = Kg + (size_t)((kt << 6) + lr) * DH + c0;
            const float* vp = Vg + (size_t)((kt << 6) + lr) * DH + c0;
            #pragma unroll
            for (int q = 0; q < 16; q += 4) {
                float4 kv = *(const float4*)(kp + q);
                Kt[(c0 + q + 0) * KV_LD + lr] = kv.x;
                Kt[(c0 + q + 1) * KV_LD + lr] = kv.y;
                Kt[(c0 + q + 2) * KV_LD + lr] = kv.z;
                Kt[(c0 + q + 3) * KV_LD + lr] = kv.w;
                *(float4*)&Vs[lr * KV_LD + c0 + q] = *(const float4*)(vp + q);
            }
        }
        __syncthreads();

        // scores s[i][j] = Q[8ty+i] . K[4tx+j]
        float s[8][4] = {};
        #pragma unroll 8
        for (int d = 0; d < 64; d++) {
            float q[8];
            *(float4*)&q[0] = *(const float4*)&Qt[d * QT_LD + (ty << 3)];
            *(float4*)&q[4] = *(const float4*)&Qt[d * QT_LD + (ty << 3) + 4];
            float4 kv = *(const float4*)&Kt[d * KV_LD + (tx << 2)];
            #pragma unroll
            for (int i = 0; i < 8; i++) {
                s[i][0] = fmaf(q[i], kv.x, s[i][0]);
                s[i][1] = fmaf(q[i], kv.y, s[i][1]);
                s[i][2] = fmaf(q[i], kv.z, s[i][2]);
                s[i][3] = fmaf(q[i], kv.w, s[i][3]);
            }
        }

        // scale (+ causal mask only on the two diagonal-overlap tiles)
        if (kt >= 2 * qt) {
            #pragma unroll
            for (int i = 0; i < 8; i++) {
                const int qg = qb + (ty << 3) + i;
                #pragma unroll
                for (int j = 0; j < 4; j++) {
                    const int kg = (kt << 6) + (tx << 2) + j;
                    s[i][j] = (kg <= qg) ? s[i][j] * scale : -1e30f;
                }
            }
        } else {
            #pragma unroll
            for (int i = 0; i < 8; i++)
                #pragma unroll
                for (int j = 0; j < 4; j++) s[i][j] *= scale;
        }

        // online softmax per row (reduce across 16 tx lanes)
        #pragma unroll
        for (int i = 0; i < 8; i++) {
            float m = fmaxf(fmaxf(s[i][0], s[i][1]), fmaxf(s[i][2], s[i][3]));
            m = fmaxf(m, __shfl_xor_sync(0xffffffffu, m, 1));
            m = fmaxf(m, __shfl_xor_sync(0xffffffffu, m, 2));
            m = fmaxf(m, __shfl_xor_sync(0xffffffffu, m, 4));
            m = fmaxf(m, __shfl_xor_sync(0xffffffffu, m, 8));
            const float mnew  = fmaxf(mrun[i], m);
            const float alpha = __expf(mrun[i] - mnew);
            float l = 0.f;
            #pragma unroll
            for (int j = 0; j < 4; j++) {
                s[i][j] = __expf(s[i][j] - mnew);
                l += s[i][j];
            }
            l += __shfl_xor_sync(0xffffffffu, l, 1);
            l += __shfl_xor_sync(0xffffffffu, l, 2);
            l += __shfl_xor_sync(0xffffffffu, l, 4);
            l += __shfl_xor_sync(0xffffffffu, l, 8);
            lrun[i] = lrun[i] * alpha + l;
            mrun[i] = mnew;
            #pragma unroll
            for (int j = 0; j < 4; j++) O[i][j] *= alpha;
            // stage P row (rows 8ty+i are produced/consumed within this warp)
            *(float4*)&Ps[((ty << 3) + i) * KV_LD + (tx << 2)] =
                make_float4(s[i][0], s[i][1], s[i][2], s[i][3]);
        }
        __syncwarp();

        // O[i][j] += sum_k P[8ty+i][k] * V[k][4tx+j]
        #pragma unroll 2
        for (int k4 = 0; k4 < 64; k4 += 4) {
            float4 p[8];
            #pragma unroll
            for (int i = 0; i < 8; i++)
                p[i] = *(const float4*)&Ps[((ty << 3) + i) * KV_LD + k4];
            #pragma unroll
            for (int t = 0; t < 4; t++) {
                float4 v = *(const float4*)&Vs[(k4 + t) * KV_LD + (tx << 2)];
                #pragma unroll
                for (int i = 0; i < 8; i++) {
                    const float pv = (t == 0) ? p[i].x : (t == 1) ? p[i].y
                                   : (t == 2) ? p[i].z : p[i].w;
                    O[i][0] = fmaf(pv, v.x, O[i][0]);
                    O[i][1] = fmaf(pv, v.y, O[i][1]);
                    O[i][2] = fmaf(pv, v.z, O[i][2]);
                    O[i][3] = fmaf(pv, v.w, O[i][3]);
                }
            }
        }
    }

    // epilogue: normalize, write to g_H [B, S, D]
    #pragma unroll
    for (int i = 0; i < 8; i++) {
        const float inv = 1.0f / lrun[i];
        float* outp = g_H + (size_t)(b * SEQ + qb + (ty << 3) + i) * DM
                          + h * DH + (tx << 2);
        *(float4*)outp = make_float4(O[i][0] * inv, O[i][1] * inv,
                                     O[i][2] * inv, O[i][3] * inv);
    }
}

// ---------------------------------------------------------------------------
extern "C" void kernel_launch(void* const* d_in, const int* in_sizes, int n_in,
                              void* d_out, int out_size) {
    const float* x  = (const float*)d_in[0];
    const float* Wq = (const float*)d_in[1];
    const float* bq = (const float*)d_in[2];
    const float* Wk = (const float*)d_in[3];
    const float* bk = (const float*)d_in[4];
    const float* Wv = (const float*)d_in[5];
    const float* bv = (const float*)d_in[6];
    const float* Wo = (const float*)d_in[7];
    const float* bo = (const float*)d_in[8];
    float* out = (float*)d_out;

    // 1. QKV projections
    dim3 gq(DM / BN, MTOT / BM, 3);
    qkv_gemm_kernel<<<gq, 256>>>(x, Wq, bq, Wk, bk, Wv, bv);

    // 2. causal flash attention
    const size_t smem = (size_t)(64 * QT_LD + 2 * 64 * KV_LD + 128 * KV_LD)
                        * sizeof(float);
    cudaFuncSetAttribute(attn_kernel, cudaFuncAttributeMaxDynamicSharedMemorySize,
                         (int)smem);
    attn_kernel<<<dim3(SEQ / QT, BATCH * NH), 256, smem>>>();

    // 3. output projection
    out_gemm_kernel<<<dim3(DM / BN, MTOT / BM), 256>>>(Wo, bo, out);
}

// round 6
// speedup vs baseline: 1.2692x; 1.0936x over previous
#include <cuda_runtime.h>
#include <cstdint>

#define BATCH 2
#define SEQ   2048
#define DM    1024
#define NH    16
#define DH    64
#define MTOT  (BATCH * SEQ)   // 4096

#define BM 128
#define BN 128
#define BK 16
#define A_LD (BK + 4)    // 20 floats/row, conflict-free A-frag LDS
#define B_LD (BN + 8)    // 136 floats/row, conflict-free B-frag LDS

// attention tiles
#define QT 128
#define QT_LD 132   // 128 + 4 pad
#define KV_LD 68    // 64 + 4 pad

// scratch (allocation-free rule: __device__ globals)
__device__ float g_Q[BATCH * NH * SEQ * DH];
__device__ float g_K[BATCH * NH * SEQ * DH];
__device__ float g_V[BATCH * NH * SEQ * DH];
__device__ float g_H[MTOT * DM];

// ---------------------------------------------------------------------------
// cp.async helpers
// ---------------------------------------------------------------------------
__device__ __forceinline__ uint32_t smaddr(const void* p) {
    return (uint32_t)__cvta_generic_to_shared(p);
}
__device__ __forceinline__ void cpa16(uint32_t s, const void* g) {
    asm volatile("cp.async.cg.shared.global [%0], [%1], 16;" :: "r"(s), "l"(g));
}
__device__ __forceinline__ void cpa_commit() {
    asm volatile("cp.async.commit_group;");
}
__device__ __forceinline__ void cpa_wait0() {
    asm volatile("cp.async.wait_group 0;");
}

// ---------------------------------------------------------------------------
// tf32 mma helpers
// ---------------------------------------------------------------------------
__device__ __forceinline__ void split_tf32(float v, uint32_t& hi, uint32_t& lo) {
    uint32_t h;
    asm("cvt.rna.tf32.f32 %0, %1;" : "=r"(h) : "f"(v));
    float r = v - __uint_as_float(h);
    asm("cvt.rna.tf32.f32 %0, %1;" : "=r"(lo) : "f"(r));
    hi = h;
}
__device__ __forceinline__ void mma_tf32(float d[4], const uint32_t a[4],
                                         const uint32_t b[2]) {
    asm volatile(
        "mma.sync.aligned.m16n8k8.row.col.f32.tf32.tf32.f32 "
        "{%0,%1,%2,%3}, {%4,%5,%6,%7}, {%8,%9}, {%0,%1,%2,%3};"
        : "+f"(d[0]), "+f"(d[1]), "+f"(d[2]), "+f"(d[3])
        : "r"(a[0]), "r"(a[1]), "r"(a[2]), "r"(a[3]), "r"(b[0]), "r"(b[1]));
}

// ---------------------------------------------------------------------------
// TF32 tensor-core GEMM core (3xTF32 compensated, fp32-accurate).
// CTA 128x128, 8 warps in 2(m) x 4(n); warp tile 64x32 = 4x4 m16n8k8.
// A staged row-major [m][K] (pad 4), B staged [k][N] (pad 8), cp.async both.
// ---------------------------------------------------------------------------
__device__ __forceinline__ void mma_gemm_tile(const float* __restrict__ A,
                                              const float* __restrict__ B,
                                              int m0, int n0, int lda, int ldb,
                                              float acc[4][4][4]) {
    __shared__ __align__(16) float As[2][BM][A_LD];
    __shared__ __align__(16) float Bs[2][BK][B_LD];

    const int tid  = threadIdx.x;
    const int lane = tid & 31;
    const int warp = tid >> 5;
    const int wm   = warp & 1;        // 0..1
    const int wn   = warp >> 1;       // 0..3

    // loader coords
    const int ar = tid >> 1;          // 0..127
    const int ac = (tid & 1) << 3;    // 0 or 8
    const int br = tid >> 4;          // 0..15
    const int bc = (tid & 15) << 3;   // 0..120

    const float* Ap = A + (size_t)(m0 + ar) * lda + ac;
    const float* Bp = B + (size_t)br * ldb + n0 + bc;

    // fragment coords
    const int frow = lane >> 2;       // 0..7
    const int fk   = lane & 3;        // 0..3
    const int abase = wm * 64 + frow;
    const int bbase = wn * 32 + frow;

    // prologue: tile 0
    cpa16(smaddr(&As[0][ar][ac]),     Ap);
    cpa16(smaddr(&As[0][ar][ac + 4]), Ap + 4);
    cpa16(smaddr(&Bs[0][br][bc]),     Bp);
    cpa16(smaddr(&Bs[0][br][bc + 4]), Bp + 4);
    cpa_commit();
    cpa_wait0();
    __syncthreads();

    int buf = 0;
    for (int kt = BK; kt <= DM; kt += BK) {
        const bool more = (kt < DM);
        if (more) {
            const float* ap = Ap + kt;
            const float* bp = Bp + (size_t)kt * ldb;
            cpa16(smaddr(&As[buf ^ 1][ar][ac]),     ap);
            cpa16(smaddr(&As[buf ^ 1][ar][ac + 4]), ap + 4);
            cpa16(smaddr(&Bs[buf ^ 1][br][bc]),     bp);
            cpa16(smaddr(&Bs[buf ^ 1][br][bc + 4]), bp + 4);
            cpa_commit();
        }
        #pragma unroll
        for (int ks = 0; ks < BK / 8; ks++) {
            const int k0 = ks * 8 + fk;
            // B fragments (hi/lo) for all 4 n-tiles
            uint32_t bh[4][2], bl[4][2];
            #pragma unroll
            for (int nt = 0; nt < 4; nt++) {
                float b0 = Bs[buf][k0][bbase + nt * 8];
                float b1 = Bs[buf][k0 + 4][bbase + nt * 8];
                split_tf32(b0, bh[nt][0], bl[nt][0]);
                split_tf32(b1, bh[nt][1], bl[nt][1]);
            }
            #pragma unroll
            for (int mt = 0; mt < 4; mt++) {
                const int r0 = abase + mt * 16;
                float a0 = As[buf][r0][k0];
                float a1 = As[buf][r0 + 8][k0];
                float a2 = As[buf][r0][k0 + 4];
                float a3 = As[buf][r0 + 8][k0 + 4];
                uint32_t ah[4], al[4];
                split_tf32(a0, ah[0], al[0]);
                split_tf32(a1, ah[1], al[1]);
                split_tf32(a2, ah[2], al[2]);
                split_tf32(a3, ah[3], al[3]);
                #pragma unroll
                for (int nt = 0; nt < 4; nt++) {
                    mma_tf32(acc[mt][nt], ah, bh[nt]);
                    mma_tf32(acc[mt][nt], al, bh[nt]);
                    mma_tf32(acc[mt][nt], ah, bl[nt]);
                }
            }
        }
        if (more) {
            buf ^= 1;
            cpa_wait0();
            __syncthreads();
        }
    }
}

// ---------------------------------------------------------------------------
// QKV projections: y = x @ W + b, scattered to [B, H, S, Dh]
// ---------------------------------------------------------------------------
__global__ __launch_bounds__(256, 2)
void qkv_gemm_kernel(const float* __restrict__ x,
                     const float* __restrict__ Wq, const float* __restrict__ bq,
                     const float* __restrict__ Wk, const float* __restrict__ bk,
                     const float* __restrict__ Wv, const float* __restrict__ bv) {
    const int m0 = blockIdx.y << 7;
    const int n0 = blockIdx.x << 7;
    const int which = blockIdx.z;
    const float* W    = (which == 0) ? Wq : (which == 1) ? Wk : Wv;
    const float* bias = (which == 0) ? bq : (which == 1) ? bk : bv;
    float* out        = (which == 0) ? g_Q : (which == 1) ? g_K : g_V;

    float acc[4][4][4] = {};
    mma_gemm_tile(x, W, m0, n0, DM, DM, acc);

    const int lane = threadIdx.x & 31;
    const int warp = threadIdx.x >> 5;
    const int wm   = warp & 1;
    const int wn   = warp >> 1;

    #pragma unroll
    for (int mt = 0; mt < 4; mt++) {
        #pragma unroll
        for (int nt = 0; nt < 4; nt++) {
            const int n = n0 + wn * 32 + nt * 8 + ((lane & 3) << 1);
            const int h = n >> 6;
            const int d = n & 63;
            const float bn0 = bias[n], bn1 = bias[n + 1];
            #pragma unroll
            for (int half = 0; half < 2; half++) {
                const int m = m0 + wm * 64 + mt * 16 + (lane >> 2) + half * 8;
                const int b = m >> 11;
                const int s = m & (SEQ - 1);
                float2 v = make_float2(acc[mt][nt][half * 2 + 0] + bn0,
                                       acc[mt][nt][half * 2 + 1] + bn1);
                *(float2*)&out[((size_t)((b * NH + h) * SEQ + s) << 6) + d] = v;
            }
        }
    }
}

// ---------------------------------------------------------------------------
// Output projection: out = g_H @ Wo + bo
// ---------------------------------------------------------------------------
__global__ __launch_bounds__(256, 2)
void out_gemm_kernel(const float* __restrict__ Wo, const float* __restrict__ bo,
                     float* __restrict__ out) {
    const int m0 = blockIdx.y << 7;
    const int n0 = blockIdx.x << 7;

    float acc[4][4][4] = {};
    mma_gemm_tile(g_H, Wo, m0, n0, DM, DM, acc);

    const int lane = threadIdx.x & 31;
    const int warp = threadIdx.x >> 5;
    const int wm   = warp & 1;
    const int wn   = warp >> 1;

    #pragma unroll
    for (int mt = 0; mt < 4; mt++) {
        #pragma unroll
        for (int nt = 0; nt < 4; nt++) {
            const int n = n0 + wn * 32 + nt * 8 + ((lane & 3) << 1);
            const float bn0 = bo[n], bn1 = bo[n + 1];
            #pragma unroll
            for (int half = 0; half < 2; half++) {
                const int m = m0 + wm * 64 + mt * 16 + (lane >> 2) + half * 8;
                float2 v = make_float2(acc[mt][nt][half * 2 + 0] + bn0,
                                       acc[mt][nt][half * 2 + 1] + bn1);
                *(float2*)&out[(size_t)m * DM + n] = v;
            }
        }
    }
}

// ---------------------------------------------------------------------------
// Causal flash attention: q-tile 128 x k-tile 64, 256 threads. (unchanged R4)
// ---------------------------------------------------------------------------
__global__ __launch_bounds__(256, 2)
void attn_kernel() {
    extern __shared__ float smf[];
    float* Qt = smf;                   // [64][QT_LD]  Qt[d][r]
    float* Kt = Qt + 64 * QT_LD;       // [64][KV_LD]  Kt[d][c]
    float* Vs = Kt + 64 * KV_LD;       // [64][KV_LD]  Vs[k][d]
    float* Ps = Vs + 64 * KV_LD;       // [128][KV_LD] Ps[r][k]

    const int qt = (gridDim.x - 1) - blockIdx.x;  // heavy tiles first
    const int bh = blockIdx.y;
    const int b  = bh / NH;
    const int h  = bh % NH;
    const int qb = qt * QT;

    const float* Qg = g_Q + (size_t)(bh * SEQ + qb) * DH;
    const float* Kg = g_K + (size_t)bh * SEQ * DH;
    const float* Vg = g_V + (size_t)bh * SEQ * DH;

    const int tid = threadIdx.x;
    const int ty  = tid >> 4;
    const int tx  = tid & 15;

    {
        const int r  = tid >> 1;
        const int c0 = (tid & 1) << 5;
        const float* qp = Qg + (size_t)r * DH + c0;
        #pragma unroll
        for (int q = 0; q < 32; q += 4) {
            float4 v = *(const float4*)(qp + q);
            Qt[(c0 + q + 0) * QT_LD + r] = v.x;
            Qt[(c0 + q + 1) * QT_LD + r] = v.y;
            Qt[(c0 + q + 2) * QT_LD + r] = v.z;
            Qt[(c0 + q + 3) * QT_LD + r] = v.w;
        }
    }

    float O[8][4];
    float mrun[8], lrun[8];
    #pragma unroll
    for (int i = 0; i < 8; i++) {
        mrun[i] = -1e30f; lrun[i] = 0.f;
        #pragma unroll
        for (int j = 0; j < 4; j++) O[i][j] = 0.f;
    }
    const float scale = 0.125f;
    const int ktmax = 2 * qt + 1;

    for (int kt = 0; kt <= ktmax; kt++) {
        __syncthreads();
        {
            const int lr = tid >> 2;
            const int c0 = (tid & 3) << 4;
            const float* kp = Kg + (size_t)((kt << 6) + lr) * DH + c0;
            const float* vp = Vg + (size_t)((kt << 6) + lr) * DH + c0;
            #pragma unroll
            for (int q = 0; q < 16; q += 4) {
                float4 kv = *(const float4*)(kp + q);
                Kt[(c0 + q + 0) * KV_LD + lr] = kv.x;
                Kt[(c0 + q + 1) * KV_LD + lr] = kv.y;
                Kt[(c0 + q + 2) * KV_LD + lr] = kv.z;
                Kt[(c0 + q + 3) * KV_LD + lr] = kv.w;
                *(float4*)&Vs[lr * KV_LD + c0 + q] = *(const float4*)(vp + q);
            }
        }
        __syncthreads();

        float s[8][4] = {};
        #pragma unroll 8
        for (int d = 0; d < 64; d++) {
            float q[8];
            *(float4*)&q[0] = *(const float4*)&Qt[d * QT_LD + (ty << 3)];
            *(float4*)&q[4] = *(const float4*)&Qt[d * QT_LD + (ty << 3) + 4];
            float4 kv = *(const float4*)&Kt[d * KV_LD + (tx << 2)];
            #pragma unroll
            for (int i = 0; i < 8; i++) {
                s[i][0] = fmaf(q[i], kv.x, s[i][0]);
                s[i][1] = fmaf(q[i], kv.y, s[i][1]);
                s[i][2] = fmaf(q[i], kv.z, s[i][2]);
                s[i][3] = fmaf(q[i], kv.w, s[i][3]);
            }
        }

        if (kt >= 2 * qt) {
            #pragma unroll
            for (int i = 0; i < 8; i++) {
                const int qg = qb + (ty << 3) + i;
                #pragma unroll
                for (int j = 0; j < 4; j++) {
                    const int kg = (kt << 6) + (tx << 2) + j;
                    s[i][j] = (kg <= qg) ? s[i][j] * scale : -1e30f;
                }
            }
        } else {
            #pragma unroll
            for (int i = 0; i < 8; i++)
                #pragma unroll
                for (int j = 0; j < 4; j++) s[i][j] *= scale;
        }

        #pragma unroll
        for (int i = 0; i < 8; i++) {
            float m = fmaxf(fmaxf(s[i][0], s[i][1]), fmaxf(s[i][2], s[i][3]));
            m = fmaxf(m, __shfl_xor_sync(0xffffffffu, m, 1));
            m = fmaxf(m, __shfl_xor_sync(0xffffffffu, m, 2));
            m = fmaxf(m, __shfl_xor_sync(0xffffffffu, m, 4));
            m = fmaxf(m, __shfl_xor_sync(0xffffffffu, m, 8));
            const float mnew  = fmaxf(mrun[i], m);
            const float alpha = __expf(mrun[i] - mnew);
            float l = 0.f;
            #pragma unroll
            for (int j = 0; j < 4; j++) {
                s[i][j] = __expf(s[i][j] - mnew);
                l += s[i][j];
            }
            l += __shfl_xor_sync(0xffffffffu, l, 1);
            l += __shfl_xor_sync(0xffffffffu, l, 2);
            l += __shfl_xor_sync(0xffffffffu, l, 4);
            l += __shfl_xor_sync(0xffffffffu, l, 8);
            lrun[i] = lrun[i] * alpha + l;
            mrun[i] = mnew;
            #pragma unroll
            for (int j = 0; j < 4; j++) O[i][j] *= alpha;
            *(float4*)&Ps[((ty << 3) + i) * KV_LD + (tx << 2)] =
                make_float4(s[i][0], s[i][1], s[i][2], s[i][3]);
        }
        __syncwarp();

        #pragma unroll 2
        for (int k4 = 0; k4 < 64; k4 += 4) {
            float4 p[8];
            #pragma unroll
            for (int i = 0; i < 8; i++)
                p[i] = *(const float4*)&Ps[((ty << 3) + i) * KV_LD + k4];
            #pragma unroll
            for (int t = 0; t < 4; t++) {
                float4 v = *(const float4*)&Vs[(k4 + t) * KV_LD + (tx << 2)];
                #pragma unroll
                for (int i = 0; i < 8; i++) {
                    const float pv = (t == 0) ? p[i].x : (t == 1) ? p[i].y
                                   : (t == 2) ? p[i].z : p[i].w;
                    O[i][0] = fmaf(pv, v.x, O[i][0]);
                    O[i][1] = fmaf(pv, v.y, O[i][1]);
                    O[i][2] = fmaf(pv, v.z, O[i][2]);
                    O[i][3] = fmaf(pv, v.w, O[i][3]);
                }
            }
        }
    }

    #pragma unroll
    for (int i = 0; i < 8; i++) {
        const float inv = 1.0f / lrun[i];
        float* outp = g_H + (size_t)(b * SEQ + qb + (ty << 3) + i) * DM
                          + h * DH + (tx << 2);
        *(float4*)outp = make_float4(O[i][0] * inv, O[i][1] * inv,
                                     O[i][2] * inv, O[i][3] * inv);
    }
}

// ---------------------------------------------------------------------------
extern "C" void kernel_launch(void* const* d_in, const int* in_sizes, int n_in,
                              void* d_out, int out_size) {
    const float* x  = (const float*)d_in[0];
    const float* Wq = (const float*)d_in[1];
    const float* bq = (const float*)d_in[2];
    const float* Wk = (const float*)d_in[3];
    const float* bk = (const float*)d_in[4];
    const float* Wv = (const float*)d_in[5];
    const float* bv = (const float*)d_in[6];
    const float* Wo = (const float*)d_in[7];
    const float* bo = (const float*)d_in[8];
    float* out = (float*)d_out;

    // 1. QKV projections (tf32 tensor cores, 3xTF32)
    dim3 gq(DM / BN, MTOT / BM, 3);
    qkv_gemm_kernel<<<gq, 256>>>(x, Wq, bq, Wk, bk, Wv, bv);

    // 2. causal flash attention
    const size_t smem = (size_t)(64 * QT_LD + 2 * 64 * KV_LD + 128 * KV_LD)
                        * sizeof(float);
    cudaFuncSetAttribute(attn_kernel, cudaFuncAttributeMaxDynamicSharedMemorySize,
                         (int)smem);
    attn_kernel<<<dim3(SEQ / QT, BATCH * NH), 256, smem>>>();

    // 3. output projection (tf32 tensor cores, 3xTF32)
    out_gemm_kernel<<<dim3(DM / BN, MTOT / BM), 256>>>(Wo, bo, out);
}